// round 8
// baseline (speedup 1.0000x reference)
#include <cuda_runtime.h>
#include <cuda_bf16.h>
#include <cstdint>

typedef unsigned long long ull;

#define N_PTS 8192
#define DIM   128
#define EMB   16

// Scratch (device globals — no allocation allowed)
__device__ __align__(16) float g_z[N_PTS * EMB];
__device__ float g_sq[N_PTS];
__device__ float g_rowsum[N_PTS];

__device__ __forceinline__ float frcp(float x) {
    float r;
    asm("rcp.approx.ftz.f32 %0, %1;" : "=f"(r) : "f"(x));
    return r;
}
__device__ __forceinline__ void fma2(ull &d, ull a, ull b) {
    asm("fma.rn.f32x2 %0, %1, %2, %0;" : "+l"(d) : "l"(a), "l"(b));
}
__device__ __forceinline__ ull add2(ull a, ull b) {
    ull d;
    asm("add.rn.f32x2 %0, %1, %2;" : "=l"(d) : "l"(a), "l"(b));
    return d;
}
__device__ __forceinline__ ull mul2(ull a, ull b) {
    ull d;
    asm("mul.rn.f32x2 %0, %1, %2;" : "=l"(d) : "l"(a), "l"(b));
    return d;
}
__device__ __forceinline__ void unpack2(ull v, float &lo, float &hi) {
    asm("mov.b64 {%0, %1}, %2;" : "=f"(lo), "=f"(hi) : "l"(v));
}
__device__ __forceinline__ ull bcast2(float x) {
    ull v;
    asm("mov.b64 %0, {%1, %1};" : "=l"(v) : "f"(x));
    return v;
}
__device__ __forceinline__ ull pack2f(float lo, float hi) {
    ull v;
    asm("mov.b64 %0, {%1, %2};" : "=l"(v) : "f"(lo), "f"(hi));
    return v;
}

// triangular linear block id -> (row r, col c) with c >= r, 128x128 tile grid
__device__ __forceinline__ int tri_off128(int r) { return (r * (257 - r)) >> 1; }
__device__ __forceinline__ void tri_decode128(int b, int &r, int &c) {
    int rr = (int)((257.0f - sqrtf(66049.0f - 8.0f * (float)b)) * 0.5f);
    if (rr < 0) rr = 0;
    if (rr > 127) rr = 127;
    while (rr < 127 && tri_off128(rr + 1) <= b) rr++;
    while (rr > 0 && tri_off128(rr) > b) rr--;
    r = rr;
    c = rr + (b - tri_off128(rr));
}

// ===========================================================================
// Kernel 0: zero the rowsum accumulators (separate launch)
// ===========================================================================
__global__ void zero_kernel()
{
    int gid = blockIdx.x * 1024 + threadIdx.x;
    if (gid < N_PTS) g_rowsum[gid] = 0.0f;
}

// ===========================================================================
// Encoder: 256 blocks x 256 threads, 32 rows/block. (R5 version)
// ===========================================================================
#define OFF_W1   0            // float[128][64]   32768
#define OFF_X    32768        // float[32][132]   16896
#define OFF_W2   49664        // float[64][32]     8192
#define OFF_W3   57856        // float[32][16]     2048
#define OFF_W4   59904        // float[16][16]     1024
#define OFF_B1   60928        // 256
#define OFF_B2   61184        // 128
#define OFF_B3   61312        // 64
#define OFF_B4   61376        // 64
#define OFF_E1   61440        // float[32][68]     8704
#define OFF_E2   70144        // float[32][36]     4608
#define OFF_E3   74752        // float[32][20]     2560
#define ENC_SMEM 77312

__global__ __launch_bounds__(256) void encoder_kernel(
    const float* __restrict__ x,
    const float* __restrict__ W1, const float* __restrict__ b1,
    const float* __restrict__ W2, const float* __restrict__ b2,
    const float* __restrict__ W3, const float* __restrict__ b3,
    const float* __restrict__ W4, const float* __restrict__ b4)
{
    extern __shared__ char dyn[];
    float* sW1 = (float*)(dyn + OFF_W1);
    float* sx  = (float*)(dyn + OFF_X);
    float* sW2 = (float*)(dyn + OFF_W2);
    float* sW3 = (float*)(dyn + OFF_W3);
    float* sW4 = (float*)(dyn + OFF_W4);
    float* sb1 = (float*)(dyn + OFF_B1);
    float* sb2 = (float*)(dyn + OFF_B2);
    float* sb3 = (float*)(dyn + OFF_B3);
    float* sb4 = (float*)(dyn + OFF_B4);
    float* e1  = (float*)(dyn + OFF_E1);
    float* e2  = (float*)(dyn + OFF_E2);
    float* e3  = (float*)(dyn + OFF_E3);

    const int t  = threadIdx.x;
    const int i0 = blockIdx.x * 32;

    {
        const ulonglong2* s = (const ulonglong2*)W1;
        ulonglong2* d = (ulonglong2*)sW1;
        #pragma unroll
        for (int r = 0; r < 8; r++) d[t + r * 256] = s[t + r * 256];
    }
    {
        const float4* x4 = (const float4*)(x + (size_t)i0 * DIM);
        #pragma unroll
        for (int r = 0; r < 4; r++) {
            int idx = t + r * 256;
            int row = idx >> 5, c = idx & 31;
            *(float4*)&sx[row * 132 + c * 4] = x4[idx];
        }
    }
    {
        const float4* s = (const float4*)W2;
        float4* d = (float4*)sW2;
        d[t] = s[t]; d[t + 256] = s[t + 256];
    }
    if (t < 128) ((float4*)sW3)[t] = ((const float4*)W3)[t];
    if (t < 64)  ((float4*)sW4)[t] = ((const float4*)W4)[t];
    if (t < 64) sb1[t] = b1[t];
    if (t < 32) sb2[t] = b2[t];
    if (t < 16) { sb3[t] = b3[t]; sb4[t] = b4[t]; }
    __syncthreads();

    {
        const int og = t & 15, rg = t >> 4;
        const int r0 = rg * 2, r1 = r0 + 1;
        ull a00 = ((const ull*)sb1)[og * 2];
        ull a01 = ((const ull*)sb1)[og * 2 + 1];
        ull a10 = a00, a11 = a01;
        const ull* w1u = (const ull*)sW1;
        #pragma unroll 4
        for (int k4 = 0; k4 < 32; k4++) {
            float4 x0 = *(const float4*)&sx[r0 * 132 + k4 * 4];
            float4 x1 = *(const float4*)&sx[r1 * 132 + k4 * 4];
            float xs0[4] = {x0.x, x0.y, x0.z, x0.w};
            float xs1[4] = {x1.x, x1.y, x1.z, x1.w};
            #pragma unroll
            for (int c = 0; c < 4; c++) {
                ulonglong2 w = *(const ulonglong2*)&w1u[(k4 * 4 + c) * 32 + og * 2];
                ull v0 = bcast2(xs0[c]);
                ull v1 = bcast2(xs1[c]);
                fma2(a00, v0, w.x); fma2(a01, v0, w.y);
                fma2(a10, v1, w.x); fma2(a11, v1, w.y);
            }
        }
        float p, q, r, s;
        unpack2(a00, p, q); unpack2(a01, r, s);
        *(float4*)&e1[r0 * 68 + og * 4] =
            make_float4(fmaxf(p, 0.f), fmaxf(q, 0.f), fmaxf(r, 0.f), fmaxf(s, 0.f));
        unpack2(a10, p, q); unpack2(a11, r, s);
        *(float4*)&e1[r1 * 68 + og * 4] =
            make_float4(fmaxf(p, 0.f), fmaxf(q, 0.f), fmaxf(r, 0.f), fmaxf(s, 0.f));
    }
    __syncthreads();

    const int row = t >> 3;
    const int e   = t & 7;

    {
        ull c0 = ((const ull*)sb2)[e * 2];
        ull c1 = ((const ull*)sb2)[e * 2 + 1];
        const float* h1r = &e1[row * 68];
        const ull* w2u = (const ull*)sW2;
        #pragma unroll 4
        for (int k4 = 0; k4 < 16; k4++) {
            float4 h = *(const float4*)&h1r[k4 * 4];
            float hs[4] = {h.x, h.y, h.z, h.w};
            #pragma unroll
            for (int c = 0; c < 4; c++) {
                ulonglong2 w = *(const ulonglong2*)&w2u[(k4 * 4 + c) * 16 + e * 2];
                ull hb = bcast2(hs[c]);
                fma2(c0, hb, w.x); fma2(c1, hb, w.y);
            }
        }
        float p, q, r, s;
        unpack2(c0, p, q); unpack2(c1, r, s);
        *(float4*)&e2[row * 36 + e * 4] =
            make_float4(fmaxf(p, 0.f), fmaxf(q, 0.f), fmaxf(r, 0.f), fmaxf(s, 0.f));
    }
    __syncthreads();

    {
        ull d0 = ((const ull*)sb3)[e];
        const float* h2r = &e2[row * 36];
        const ull* w3u = (const ull*)sW3;
        #pragma unroll
        for (int k4 = 0; k4 < 8; k4++) {
            float4 h = *(const float4*)&h2r[k4 * 4];
            float hs[4] = {h.x, h.y, h.z, h.w};
            #pragma unroll
            for (int c = 0; c < 4; c++) {
                ull w = w3u[(k4 * 4 + c) * 8 + e];
                fma2(d0, bcast2(hs[c]), w);
            }
        }
        float p, q;
        unpack2(d0, p, q);
        *(float2*)&e3[row * 20 + e * 2] = make_float2(fmaxf(p, 0.f), fmaxf(q, 0.f));
    }
    __syncthreads();

    {
        ull f0 = ((const ull*)sb4)[e];
        const float* h3r = &e3[row * 20];
        const ull* w4u = (const ull*)sW4;
        #pragma unroll
        for (int k4 = 0; k4 < 4; k4++) {
            float4 h = *(const float4*)&h3r[k4 * 4];
            float hs[4] = {h.x, h.y, h.z, h.w};
            #pragma unroll
            for (int c = 0; c < 4; c++) {
                ull w = w4u[(k4 * 4 + c) * 8 + e];
                fma2(f0, bcast2(hs[c]), w);
            }
        }
        float z0, z1;
        unpack2(f0, z0, z1);
        *(float2*)&g_z[(size_t)(i0 + row) * EMB + e * 2] = make_float2(z0, z1);

        float ps = z0 * z0 + z1 * z1;
        ps += __shfl_xor_sync(0xffffffffu, ps, 1);
        ps += __shfl_xor_sync(0xffffffffu, ps, 2);
        ps += __shfl_xor_sync(0xffffffffu, ps, 4);
        if (e == 0) g_sq[i0 + row] = ps;
    }
}

// ===========================================================================
// Packed-lane pairwise machinery.
// zasm[k][i]  = (z_ik, z_ik)           dup-A, k-major, 64 rows
// zbsm[k][jp] = (z_{2jp,k}, z_{2jp+1,k}) packed-B pairs, 32 jp
// Thread (tx 0..15, ty 0..15): i = 4ty+ii, j = 4tx + {0..3} (jp = 2tx, 2tx+1)
// acc[ii*2+p] lanes are COMPLETE dots (no horizontal add needed).
// ===========================================================================
__device__ __forceinline__ void stage_a_dup(ull (*zasm)[66], int r0, int t) {
    const float4* gz4 = (const float4*)g_z;
    int i = t & 63, kq = t >> 6;
    float4 f = gz4[(size_t)(r0 + i) * 4 + kq];
    zasm[kq * 4 + 0][i] = bcast2(f.x);
    zasm[kq * 4 + 1][i] = bcast2(f.y);
    zasm[kq * 4 + 2][i] = bcast2(f.z);
    zasm[kq * 4 + 3][i] = bcast2(f.w);
}

__device__ __forceinline__ void stage_b_pack(ull (*zbsm)[34], int j0, int t) {
    if (t < 128) {
        const float4* gz4 = (const float4*)g_z;
        int jp = t & 31, kq = t >> 5;
        float4 fa = gz4[(size_t)(j0 + 2 * jp) * 4 + kq];
        float4 fb = gz4[(size_t)(j0 + 2 * jp + 1) * 4 + kq];
        zbsm[kq * 4 + 0][jp] = pack2f(fa.x, fb.x);
        zbsm[kq * 4 + 1][jp] = pack2f(fa.y, fb.y);
        zbsm[kq * 4 + 2][jp] = pack2f(fa.z, fb.z);
        zbsm[kq * 4 + 3][jp] = pack2f(fa.w, fb.w);
    }
}

__device__ __forceinline__ void mma_packed(ull* acc, const ull (*zasm)[66],
                                           const ull (*zbsm)[34], int tx, int ty) {
    #pragma unroll
    for (int k = 0; k < 16; k++) {
        ulonglong2 b01 = *(const ulonglong2*)&zbsm[k][2 * tx];
        ulonglong2 a01 = *(const ulonglong2*)&zasm[k][4 * ty];
        ulonglong2 a23 = *(const ulonglong2*)&zasm[k][4 * ty + 2];
        ull av[4] = {a01.x, a01.y, a23.x, a23.y};
        #pragma unroll
        for (int ii = 0; ii < 4; ii++) {
            fma2(acc[ii * 2 + 0], av[ii], b01.x);
            fma2(acc[ii * 2 + 1], av[ii], b01.y);
        }
    }
}

// ===========================================================================
// Kernel 2: symmetric row sums. triangular grid over 64x64 tiles (8256 blk).
// ===========================================================================
__global__ __launch_bounds__(256) void rowsum_kernel()
{
    int by, bx;
    tri_decode128(blockIdx.x, by, bx);

    __shared__ __align__(16) ull zasm[16][66];
    __shared__ __align__(16) ull zbsm[16][34];
    __shared__ __align__(16) ull sq1jp[32];   // (1+sq_j0, 1+sq_j1) packed
    __shared__ float sqis[64];
    __shared__ float rowacc[64];
    __shared__ float colacc[64];

    const int t = threadIdx.x, tx = t & 15, ty = t >> 4;
    const int i0 = by * 64, j0 = bx * 64;
    const bool diag = (bx == by);

    stage_a_dup(zasm, i0, t);
    stage_b_pack(zbsm, j0, t);
    if (t >= 128 && t < 192) sqis[t - 128] = g_sq[i0 + (t - 128)];
    else if (t >= 192 && t < 224) {
        int jp = t - 192;
        sq1jp[jp] = pack2f(1.0f + g_sq[j0 + 2 * jp], 1.0f + g_sq[j0 + 2 * jp + 1]);
    }
    else if (t >= 224) colacc[(t - 224) * 2] = 0.0f, colacc[(t - 224) * 2 + 1] = 0.0f;
    __syncthreads();

    ull acc[8];
    #pragma unroll
    for (int m = 0; m < 8; m++) acc[m] = 0ull;
    mma_packed(acc, zasm, zbsm, tx, ty);

    const ull neg2 = bcast2(-2.0f);
    ulonglong2 sj2 = *(const ulonglong2*)&sq1jp[2 * tx];
    float colp0 = 0.f, colp1 = 0.f, colp2 = 0.f, colp3 = 0.f;

    #pragma unroll
    for (int ii = 0; ii < 4; ii++) {
        const ull sid = bcast2(sqis[ty * 4 + ii]);
        ull d0 = add2(sid, sj2.x);
        ull d1 = add2(sid, sj2.y);
        fma2(d0, acc[ii * 2 + 0], neg2);
        fma2(d1, acc[ii * 2 + 1], neg2);
        float e0, e1, e2, e3;
        unpack2(d0, e0, e1);
        unpack2(d1, e2, e3);
        float n0 = frcp(e0), n1 = frcp(e1), n2 = frcp(e2), n3 = frcp(e3);

        float v = (n0 + n1) + (n2 + n3);
        v += __shfl_xor_sync(0xffffffffu, v, 1);
        v += __shfl_xor_sync(0xffffffffu, v, 2);
        v += __shfl_xor_sync(0xffffffffu, v, 4);
        v += __shfl_xor_sync(0xffffffffu, v, 8);
        if (tx == 0) rowacc[ty * 4 + ii] = v;

        colp0 += n0; colp1 += n1; colp2 += n2; colp3 += n3;
    }

    if (!diag) {
        colp0 += __shfl_xor_sync(0xffffffffu, colp0, 16);
        colp1 += __shfl_xor_sync(0xffffffffu, colp1, 16);
        colp2 += __shfl_xor_sync(0xffffffffu, colp2, 16);
        colp3 += __shfl_xor_sync(0xffffffffu, colp3, 16);
        if ((t & 16) == 0) {
            atomicAdd(&colacc[4 * tx + 0], colp0);
            atomicAdd(&colacc[4 * tx + 1], colp1);
            atomicAdd(&colacc[4 * tx + 2], colp2);
            atomicAdd(&colacc[4 * tx + 3], colp3);
        }
    }
    __syncthreads();

    if (t < 64) atomicAdd(&g_rowsum[i0 + t], rowacc[t]);
    if (!diag && t >= 64 && t < 128) atomicAdd(&g_rowsum[j0 + (t - 64)], colacc[t - 64]);
}

// ===========================================================================
// Kernel 3: symmetric writer. triangular grid (8256 blocks), 256 threads.
// ===========================================================================
__global__ __launch_bounds__(256) void writer_kernel(float* __restrict__ out)
{
    int by, bx;
    tri_decode128(blockIdx.x, by, bx);

    __shared__ __align__(16) ull zasm[16][66];
    __shared__ __align__(16) ull zbsm[16][34];
    __shared__ __align__(16) ull snum[64 * 34];   // packed num pairs, float[64][68]
    __shared__ __align__(16) ull sq1jp[32];
    __shared__ float sqis[64];
    __shared__ float rinvi[64];
    __shared__ float rinvj[64];

    const int t = threadIdx.x, tx = t & 15, ty = t >> 4;
    const int i0 = by * 64, j0 = bx * 64;
    const bool diag = (bx == by);

    stage_a_dup(zasm, i0, t);
    stage_b_pack(zbsm, j0, t);
    if (t >= 128 && t < 192) {
        sqis[t - 128] = g_sq[i0 + (t - 128)];
        rinvi[t - 128] = frcp(g_rowsum[i0 + (t - 128)]);
    } else if (t >= 192 && t < 224) {
        int jp = t - 192;
        sq1jp[jp] = pack2f(1.0f + g_sq[j0 + 2 * jp], 1.0f + g_sq[j0 + 2 * jp + 1]);
        rinvj[2 * jp]     = frcp(g_rowsum[j0 + 2 * jp]);
        rinvj[2 * jp + 1] = frcp(g_rowsum[j0 + 2 * jp + 1]);
    }
    __syncthreads();

    ull acc[8];
    #pragma unroll
    for (int m = 0; m < 8; m++) acc[m] = 0ull;
    mma_packed(acc, zasm, zbsm, tx, ty);

    const ull neg2 = bcast2(-2.0f);
    ulonglong2 sj2 = *(const ulonglong2*)&sq1jp[2 * tx];

    #pragma unroll
    for (int ii = 0; ii < 4; ii++) {
        const int irow = ty * 4 + ii;
        const ull sid = bcast2(sqis[irow]);
        const ull rv2 = bcast2(rinvi[irow]);
        ull d0 = add2(sid, sj2.x);
        ull d1 = add2(sid, sj2.y);
        fma2(d0, acc[ii * 2 + 0], neg2);
        fma2(d1, acc[ii * 2 + 1], neg2);
        float e0, e1, e2, e3;
        unpack2(d0, e0, e1);
        unpack2(d1, e2, e3);
        ull n01 = pack2f(frcp(e0), frcp(e1));
        ull n23 = pack2f(frcp(e2), frcp(e3));

        // stage packed numerators (STS.128)
        ulonglong2 nn; nn.x = n01; nn.y = n23;
        *(ulonglong2*)&snum[irow * 34 + 2 * tx] = nn;

        // normal tile store (STG.128)
        ulonglong2 vv; vv.x = mul2(n01, rv2); vv.y = mul2(n23, rv2);
        *(ulonglong2*)&out[(size_t)(i0 + irow) * N_PTS + j0 + 4 * tx] = vv;
    }

    if (!diag) {
        __syncthreads();
        const float* snf = (const float*)snum;   // float[64][68]
        #pragma unroll
        for (int ii = 0; ii < 4; ii++) {
            const int jrow = ty * 4 + ii;
            const float rvj = rinvj[jrow];
            float* orow = &out[(size_t)(j0 + jrow) * N_PTS + i0];
            orow[tx]      = snf[(tx)      * 68 + jrow] * rvj;
            orow[tx + 16] = snf[(tx + 16) * 68 + jrow] * rvj;
            orow[tx + 32] = snf[(tx + 32) * 68 + jrow] * rvj;
            orow[tx + 48] = snf[(tx + 48) * 68 + jrow] * rvj;
        }
    }
}

// ---------------------------------------------------------------------------
extern "C" void kernel_launch(void* const* d_in, const int* in_sizes, int n_in,
                              void* d_out, int out_size)
{
    const float* x  = (const float*)d_in[0];
    const float* W1 = (const float*)d_in[1];
    const float* b1 = (const float*)d_in[2];
    const float* W2 = (const float*)d_in[3];
    const float* b2 = (const float*)d_in[4];
    const float* W3 = (const float*)d_in[5];
    const float* b3 = (const float*)d_in[6];
    const float* W4 = (const float*)d_in[7];
    const float* b4 = (const float*)d_in[8];
    float* out = (float*)d_out;

    cudaFuncSetAttribute(encoder_kernel,
                         cudaFuncAttributeMaxDynamicSharedMemorySize, ENC_SMEM);

    const int n_tri = (128 * 129) / 2;  // 8256

    zero_kernel<<<8, 1024>>>();
    encoder_kernel<<<N_PTS / 32, 256, ENC_SMEM>>>(x, W1, b1, W2, b2, W3, b3, W4, b4);
    rowsum_kernel<<<n_tri, 256>>>();
    writer_kernel<<<n_tri, 256>>>(out);
}